// round 7
// baseline (speedup 1.0000x reference)
#include <cuda_runtime.h>

#define R 128
#define PROBE_BYTES (6 * R * R * 3 * 4)   // 1179648
#define FACE_BYTES  (R * R * 3 * 4)       // 196608
#define NQ_CAP 524288
#define NBUCKETS 1536                      // 8*8*4 cells * 6 faces

__device__ unsigned d_perm[NQ_CAP];
__device__ unsigned d_count[2048];
__device__ unsigned d_cursor[2048];

// ---- shared key computation: cell from xyz, face from raw l (scale-invariant) ----
__device__ __forceinline__ int query_key(const float* __restrict__ xyz,
                                         const float* __restrict__ l, int i)
{
    float px = xyz[3 * i + 0], py = xyz[3 * i + 1], pz = xyz[3 * i + 2];
    int ix0 = (int)floorf(fminf(fmaxf(px * 7.0f, 0.0f), 7.0f));
    int iy0 = (int)floorf(fminf(fmaxf(py * 7.0f, 0.0f), 7.0f));
    int iz0 = (int)floorf(fminf(fmaxf(pz * 3.0f, 0.0f), 3.0f));
    float lx = l[3 * i + 0], ly = l[3 * i + 1], lz = l[3 * i + 2];
    float ax = fabsf(lx), ay = fabsf(ly), az = fabsf(lz);
    bool is_x = (ax >= ay) && (ax >= az);
    bool is_y = (!is_x) && (ay >= az);
    int face = is_x ? (lx >= 0.0f ? 0 : 1)
             : (is_y ? (ly >= 0.0f ? 2 : 3)
                     : (lz >= 0.0f ? 4 : 5));
    return ((ix0 * 8 + iy0) * 4 + iz0) * 6 + face;
}

__global__ void zero_counts_kernel() {
    int t = blockIdx.x * blockDim.x + threadIdx.x;
    if (t < 2048) d_count[t] = 0;
}

__global__ __launch_bounds__(256) void hist_kernel(
    const float* __restrict__ xyz, const float* __restrict__ l, int n)
{
    __shared__ unsigned sh[NBUCKETS];
    for (int b = threadIdx.x; b < NBUCKETS; b += blockDim.x) sh[b] = 0;
    __syncthreads();
    int i = blockIdx.x * blockDim.x + threadIdx.x;
    if (i < n) atomicAdd(&sh[query_key(xyz, l, i)], 1u);
    __syncthreads();
    for (int b = threadIdx.x; b < NBUCKETS; b += blockDim.x)
        if (sh[b]) atomicAdd(&d_count[b], sh[b]);
}

__global__ __launch_bounds__(1024) void scan_kernel() {
    __shared__ unsigned buf[2][2048];
    int t = threadIdx.x;
    buf[0][t] = d_count[t];
    buf[0][t + 1024] = d_count[t + 1024];
    __syncthreads();
    int cur = 0;
    for (int d = 1; d < 2048; d <<= 1) {
        int nxt = cur ^ 1;
        unsigned a0 = buf[cur][t]        + ((t        >= d) ? buf[cur][t - d]        : 0u);
        unsigned a1 = buf[cur][t + 1024] + ((t + 1024 >= d) ? buf[cur][t + 1024 - d] : 0u);
        __syncthreads();
        buf[nxt][t] = a0;
        buf[nxt][t + 1024] = a1;
        __syncthreads();
        cur = nxt;
    }
    // exclusive prefix -> cursor
    d_cursor[t]        = (t == 0) ? 0u : buf[cur][t - 1];
    d_cursor[t + 1024] = buf[cur][t + 1023];
}

__global__ __launch_bounds__(256) void scatter_kernel(
    const float* __restrict__ xyz, const float* __restrict__ l, int n)
{
    int i = blockIdx.x * blockDim.x + threadIdx.x;
    if (i >= n) return;
    unsigned pos = atomicAdd(&d_cursor[query_key(xyz, l, i)], 1u);
    d_perm[pos] = i;
}

__global__ __launch_bounds__(256) void multienv_kernel(
    const float* __restrict__ xyz,
    const float* __restrict__ l,
    const float* __restrict__ base,
    float* __restrict__ out,
    int n, int use_perm)
{
    int j = blockIdx.x * blockDim.x + threadIdx.x;
    if (j >= n) return;
    int i = use_perm ? (int)d_perm[j] : j;

    // ---- direction normalize ----
    float lx = l[3 * i + 0], ly = l[3 * i + 1], lz = l[3 * i + 2];
    float dot = lx * lx + ly * ly + lz * lz;
    float inv = rsqrtf(fmaxf(dot, 1e-18f));
    float dx = lx * inv, dy = ly * inv, dz = lz * inv;

    // ---- cube face / uv (OpenGL convention) ----
    float ax = fabsf(dx), ay = fabsf(dy), az = fabsf(dz);
    bool is_x = (ax >= ay) && (ax >= az);
    bool is_y = (!is_x) && (ay >= az);
    int face;
    float ma, sc, tc;
    if (is_x) {
        face = (dx >= 0.0f) ? 0 : 1;
        ma = ax;
        sc = (dx >= 0.0f) ? -dz : dz;
        tc = -dy;
    } else if (is_y) {
        face = (dy >= 0.0f) ? 2 : 3;
        ma = ay;
        sc = dx;
        tc = (dy >= 0.0f) ? dz : -dz;
    } else {
        face = (dz >= 0.0f) ? 4 : 5;
        ma = az;
        sc = (dz >= 0.0f) ? dx : -dx;
        tc = -dy;
    }
    ma = fmaxf(ma, 1e-9f);
    float rma = __fdividef(1.0f, ma);
    float u = 0.5f * (sc * rma + 1.0f);
    float v = 0.5f * (tc * rma + 1.0f);

    // ---- bilinear texel coords ----
    float fx = u * (float)R - 0.5f;
    float fy = v * (float)R - 0.5f;
    float x0f = floorf(fx), y0f = floorf(fy);
    float tx = fx - x0f, ty = fy - y0f;
    int x0 = min(max((int)x0f, 0), R - 1);
    int x1 = min(max((int)x0f + 1, 0), R - 1);
    int y0 = min(max((int)y0f, 0), R - 1);
    int y1 = min(max((int)y0f + 1, 0), R - 1);

    int cs   = min(x0, R - 2);
    int off0 = x0 - cs;
    int off1 = x1 - cs;
    float gx0 = (off0 ? 0.0f : (1.0f - tx)) + (off1 ? 0.0f : tx);
    float gx1 = 1.0f - gx0;

    unsigned rb0 = (unsigned)face * FACE_BYTES + (unsigned)(y0 * R + cs) * 12u;
    unsigned rb1 = (unsigned)face * FACE_BYTES + (unsigned)(y1 * R + cs) * 12u;

    int k = (int)((rb0 & 15u) >> 2);   // 0..3 (same for all 16 chunks)
    bool k1 = (k == 1), k2 = (k == 2), k3 = (k == 3);

    // ---- trilinear probe corners; GRID_RES = (8,8,4) ----
    float px = xyz[3 * i + 0], py = xyz[3 * i + 1], pz = xyz[3 * i + 2];
    float cx = fminf(fmaxf(px * 7.0f, 0.0f), 7.0f);
    float cy = fminf(fmaxf(py * 7.0f, 0.0f), 7.0f);
    float cz = fminf(fmaxf(pz * 3.0f, 0.0f), 3.0f);
    int ix0 = (int)floorf(cx);
    int iy0 = (int)floorf(cy);
    int iz0 = (int)floorf(cz);
    int ix1 = min(ix0 + 1, 7);
    int iy1 = min(iy0 + 1, 7);
    int iz1 = min(iz0 + 1, 3);
    float gx = cx - (float)ix0;
    float gy = cy - (float)iy0;
    float gz = cz - (float)iz0;

    unsigned pbyte[8];
    float pw[8];
    {
        float wx0 = 1.0f - gx, wx1 = gx;
        float wy0 = 1.0f - gy, wy1 = gy;
        float wz0 = 1.0f - gz, wz1 = gz;
        unsigned bx0 = (unsigned)ix0 * 32u, bx1 = (unsigned)ix1 * 32u;
        unsigned by0 = (unsigned)iy0 * 4u,  by1 = (unsigned)iy1 * 4u;
        pbyte[0] = (bx0 + by0 + iz0) * (unsigned)PROBE_BYTES;  pw[0] = wx0 * wy0 * wz0;
        pbyte[1] = (bx0 + by0 + iz1) * (unsigned)PROBE_BYTES;  pw[1] = wx0 * wy0 * wz1;
        pbyte[2] = (bx0 + by1 + iz0) * (unsigned)PROBE_BYTES;  pw[2] = wx0 * wy1 * wz0;
        pbyte[3] = (bx0 + by1 + iz1) * (unsigned)PROBE_BYTES;  pw[3] = wx0 * wy1 * wz1;
        pbyte[4] = (bx1 + by0 + iz0) * (unsigned)PROBE_BYTES;  pw[4] = wx1 * wy0 * wz0;
        pbyte[5] = (bx1 + by0 + iz1) * (unsigned)PROBE_BYTES;  pw[5] = wx1 * wy0 * wz1;
        pbyte[6] = (bx1 + by1 + iz0) * (unsigned)PROBE_BYTES;  pw[6] = wx1 * wy1 * wz0;
        pbyte[7] = (bx1 + by1 + iz1) * (unsigned)PROBE_BYTES;  pw[7] = wx1 * wy1 * wz1;
    }
    float wsum = pw[0] + pw[1] + pw[2] + pw[3] + pw[4] + pw[5] + pw[6] + pw[7];
    float wscale = __fdividef(1.0f, fmaxf(wsum, 1e-8f));

    float wty0 = 1.0f - ty, wty1 = ty;
    const char* basec = (const char*)base;

    float acc0 = 0.0f, acc1 = 0.0f, acc2 = 0.0f;

#pragma unroll
    for (int p = 0; p < 8; p++) {
        unsigned pb = pbyte[p];
        float wp = pw[p];
#pragma unroll
        for (int r = 0; r < 2; r++) {
            unsigned s = pb + (r ? rb1 : rb0);
            unsigned f = s & ~15u;
            float4 A = __ldg((const float4*)(basec + f));
            float4 B = __ldg((const float4*)(basec + f + 16));
            float E = 0.0f;
            if (k3) E = __ldg((const float*)(basec + f + 32));

            float c0 = k1 ? A.y : A.x;  c0 = k2 ? A.z : c0;  c0 = k3 ? A.w : c0;
            float c1 = k1 ? A.z : A.y;  c1 = k2 ? A.w : c1;  c1 = k3 ? B.x : c1;
            float c2 = k1 ? A.w : A.z;  c2 = k2 ? B.x : c2;  c2 = k3 ? B.y : c2;
            float c3 = k1 ? B.x : A.w;  c3 = k2 ? B.y : c3;  c3 = k3 ? B.z : c3;
            float c4 = k1 ? B.y : B.x;  c4 = k2 ? B.z : c4;  c4 = k3 ? B.w : c4;
            float c5 = k1 ? B.z : B.y;  c5 = k2 ? B.w : c5;  c5 = k3 ? E   : c5;

            float w = wp * (r ? wty1 : wty0);
            acc0 = fmaf(w, fmaf(gx0, c0, gx1 * c3), acc0);
            acc1 = fmaf(w, fmaf(gx0, c1, gx1 * c4), acc1);
            acc2 = fmaf(w, fmaf(gx0, c2, gx1 * c5), acc2);
        }
    }
    acc0 *= wscale; acc1 *= wscale; acc2 *= wscale;

    out[3 * i + 0] = __fdividef(10.0f, 1.0f + __expf(-acc0));
    out[3 * i + 1] = __fdividef(10.0f, 1.0f + __expf(-acc1));
    out[3 * i + 2] = __fdividef(10.0f, 1.0f + __expf(-acc2));
}

extern "C" void kernel_launch(void* const* d_in, const int* in_sizes, int n_in,
                              void* d_out, int out_size) {
    const float* xyz  = (const float*)d_in[0];
    const float* l    = (const float*)d_in[1];
    const float* base = (const float*)d_in[2];
    float* out = (float*)d_out;
    int n = in_sizes[0] / 3;
    int threads = 256;
    int blocks = (n + threads - 1) / threads;

    if (n <= NQ_CAP) {
        zero_counts_kernel<<<2, 1024>>>();
        hist_kernel<<<blocks, threads>>>(xyz, l, n);
        scan_kernel<<<1, 1024>>>();
        scatter_kernel<<<blocks, threads>>>(xyz, l, n);
        multienv_kernel<<<blocks, threads>>>(xyz, l, base, out, n, 1);
    } else {
        multienv_kernel<<<blocks, threads>>>(xyz, l, base, out, n, 0);
    }
}

// round 8
// speedup vs baseline: 1.0271x; 1.0271x over previous
#include <cuda_runtime.h>

#define R 128
#define PROBE_BYTES (6 * R * R * 3 * 4)   // 1179648
#define FACE_BYTES  (R * R * 3 * 4)       // 196608
#define NQ_CAP 524288
#define NBUCKETS 1536                      // 8*8*4 cells * 6 faces
#define PAD 32                             // 128B stride: one counter per sector

__device__ unsigned d_perm[NQ_CAP];
__device__ unsigned d_count[NBUCKETS * PAD];
__device__ unsigned d_cursor[NBUCKETS * PAD];

// ---- shared key computation: cell from xyz, face from raw l (scale-invariant) ----
__device__ __forceinline__ int query_key(const float* __restrict__ xyz,
                                         const float* __restrict__ l, int i)
{
    float px = xyz[3 * i + 0], py = xyz[3 * i + 1], pz = xyz[3 * i + 2];
    int ix0 = (int)floorf(fminf(fmaxf(px * 7.0f, 0.0f), 7.0f));
    int iy0 = (int)floorf(fminf(fmaxf(py * 7.0f, 0.0f), 7.0f));
    int iz0 = (int)floorf(fminf(fmaxf(pz * 3.0f, 0.0f), 3.0f));
    float lx = l[3 * i + 0], ly = l[3 * i + 1], lz = l[3 * i + 2];
    float ax = fabsf(lx), ay = fabsf(ly), az = fabsf(lz);
    bool is_x = (ax >= ay) && (ax >= az);
    bool is_y = (!is_x) && (ay >= az);
    int face = is_x ? (lx >= 0.0f ? 0 : 1)
             : (is_y ? (ly >= 0.0f ? 2 : 3)
                     : (lz >= 0.0f ? 4 : 5));
    return ((ix0 * 8 + iy0) * 4 + iz0) * 6 + face;
}

__global__ void zero_counts_kernel() {
    int t = blockIdx.x * blockDim.x + threadIdx.x;
    if (t < NBUCKETS * PAD) d_count[t] = 0;
}

__global__ __launch_bounds__(256) void hist_kernel(
    const float* __restrict__ xyz, const float* __restrict__ l, int n)
{
    __shared__ unsigned sh[NBUCKETS];
    for (int b = threadIdx.x; b < NBUCKETS; b += blockDim.x) sh[b] = 0;
    __syncthreads();
    int i = blockIdx.x * blockDim.x + threadIdx.x;
    if (i < n) atomicAdd(&sh[query_key(xyz, l, i)], 1u);
    __syncthreads();
    for (int b = threadIdx.x; b < NBUCKETS; b += blockDim.x)
        if (sh[b]) atomicAdd(&d_count[b * PAD], sh[b]);
}

__global__ __launch_bounds__(1024) void scan_kernel() {
    __shared__ unsigned buf[2][NBUCKETS];
    int t = threadIdx.x;
    // load 1536 padded counters
    buf[0][t] = d_count[t * PAD];
    if (t < NBUCKETS - 1024) buf[0][t + 1024] = d_count[(t + 1024) * PAD];
    __syncthreads();
    int cur = 0;
    for (int d = 1; d < NBUCKETS; d <<= 1) {
        int nxt = cur ^ 1;
        unsigned a0 = buf[cur][t] + ((t >= d) ? buf[cur][t - d] : 0u);
        unsigned a1 = 0u;
        if (t < NBUCKETS - 1024)
            a1 = buf[cur][t + 1024] + ((t + 1024 >= d) ? buf[cur][t + 1024 - d] : 0u);
        __syncthreads();
        buf[nxt][t] = a0;
        if (t < NBUCKETS - 1024) buf[nxt][t + 1024] = a1;
        __syncthreads();
        cur = nxt;
    }
    // exclusive prefix -> padded cursor
    d_cursor[t * PAD] = (t == 0) ? 0u : buf[cur][t - 1];
    if (t < NBUCKETS - 1024)
        d_cursor[(t + 1024) * PAD] = buf[cur][t + 1023];
}

__global__ __launch_bounds__(256) void scatter_kernel(
    const float* __restrict__ xyz, const float* __restrict__ l, int n)
{
    int i = blockIdx.x * blockDim.x + threadIdx.x;
    if (i >= n) return;
    unsigned pos = atomicAdd(&d_cursor[query_key(xyz, l, i) * PAD], 1u);
    d_perm[pos] = i;
}

__global__ __launch_bounds__(256) void multienv_kernel(
    const float* __restrict__ xyz,
    const float* __restrict__ l,
    const float* __restrict__ base,
    float* __restrict__ out,
    int n, int use_perm)
{
    int j = blockIdx.x * blockDim.x + threadIdx.x;
    if (j >= n) return;
    int i = use_perm ? (int)d_perm[j] : j;

    // ---- direction normalize ----
    float lx = l[3 * i + 0], ly = l[3 * i + 1], lz = l[3 * i + 2];
    float dot = lx * lx + ly * ly + lz * lz;
    float inv = rsqrtf(fmaxf(dot, 1e-18f));
    float dx = lx * inv, dy = ly * inv, dz = lz * inv;

    // ---- cube face / uv (OpenGL convention) ----
    float ax = fabsf(dx), ay = fabsf(dy), az = fabsf(dz);
    bool is_x = (ax >= ay) && (ax >= az);
    bool is_y = (!is_x) && (ay >= az);
    int face;
    float ma, sc, tc;
    if (is_x) {
        face = (dx >= 0.0f) ? 0 : 1;
        ma = ax;
        sc = (dx >= 0.0f) ? -dz : dz;
        tc = -dy;
    } else if (is_y) {
        face = (dy >= 0.0f) ? 2 : 3;
        ma = ay;
        sc = dx;
        tc = (dy >= 0.0f) ? dz : -dz;
    } else {
        face = (dz >= 0.0f) ? 4 : 5;
        ma = az;
        sc = (dz >= 0.0f) ? dx : -dx;
        tc = -dy;
    }
    ma = fmaxf(ma, 1e-9f);
    float rma = __fdividef(1.0f, ma);
    float u = 0.5f * (sc * rma + 1.0f);
    float v = 0.5f * (tc * rma + 1.0f);

    // ---- bilinear texel coords ----
    float fx = u * (float)R - 0.5f;
    float fy = v * (float)R - 0.5f;
    float x0f = floorf(fx), y0f = floorf(fy);
    float tx = fx - x0f, ty = fy - y0f;
    int x0 = min(max((int)x0f, 0), R - 1);
    int x1 = min(max((int)x0f + 1, 0), R - 1);
    int y0 = min(max((int)y0f, 0), R - 1);
    int y1 = min(max((int)y0f + 1, 0), R - 1);

    int cs   = min(x0, R - 2);
    int off0 = x0 - cs;
    int off1 = x1 - cs;
    float gx0 = (off0 ? 0.0f : (1.0f - tx)) + (off1 ? 0.0f : tx);
    float gx1 = 1.0f - gx0;

    unsigned rb0 = (unsigned)face * FACE_BYTES + (unsigned)(y0 * R + cs) * 12u;
    unsigned rb1 = (unsigned)face * FACE_BYTES + (unsigned)(y1 * R + cs) * 12u;

    int k = (int)((rb0 & 15u) >> 2);   // 0..3 (same for all 16 chunks)
    bool k1 = (k == 1), k2 = (k == 2), k3 = (k == 3);

    // ---- trilinear probe corners; GRID_RES = (8,8,4) ----
    float px = xyz[3 * i + 0], py = xyz[3 * i + 1], pz = xyz[3 * i + 2];
    float cx = fminf(fmaxf(px * 7.0f, 0.0f), 7.0f);
    float cy = fminf(fmaxf(py * 7.0f, 0.0f), 7.0f);
    float cz = fminf(fmaxf(pz * 3.0f, 0.0f), 3.0f);
    int ix0 = (int)floorf(cx);
    int iy0 = (int)floorf(cy);
    int iz0 = (int)floorf(cz);
    int ix1 = min(ix0 + 1, 7);
    int iy1 = min(iy0 + 1, 7);
    int iz1 = min(iz0 + 1, 3);
    float gx = cx - (float)ix0;
    float gy = cy - (float)iy0;
    float gz = cz - (float)iz0;

    unsigned pbyte[8];
    float pw[8];
    {
        float wx0 = 1.0f - gx, wx1 = gx;
        float wy0 = 1.0f - gy, wy1 = gy;
        float wz0 = 1.0f - gz, wz1 = gz;
        unsigned bx0 = (unsigned)ix0 * 32u, bx1 = (unsigned)ix1 * 32u;
        unsigned by0 = (unsigned)iy0 * 4u,  by1 = (unsigned)iy1 * 4u;
        pbyte[0] = (bx0 + by0 + iz0) * (unsigned)PROBE_BYTES;  pw[0] = wx0 * wy0 * wz0;
        pbyte[1] = (bx0 + by0 + iz1) * (unsigned)PROBE_BYTES;  pw[1] = wx0 * wy0 * wz1;
        pbyte[2] = (bx0 + by1 + iz0) * (unsigned)PROBE_BYTES;  pw[2] = wx0 * wy1 * wz0;
        pbyte[3] = (bx0 + by1 + iz1) * (unsigned)PROBE_BYTES;  pw[3] = wx0 * wy1 * wz1;
        pbyte[4] = (bx1 + by0 + iz0) * (unsigned)PROBE_BYTES;  pw[4] = wx1 * wy0 * wz0;
        pbyte[5] = (bx1 + by0 + iz1) * (unsigned)PROBE_BYTES;  pw[5] = wx1 * wy0 * wz1;
        pbyte[6] = (bx1 + by1 + iz0) * (unsigned)PROBE_BYTES;  pw[6] = wx1 * wy1 * wz0;
        pbyte[7] = (bx1 + by1 + iz1) * (unsigned)PROBE_BYTES;  pw[7] = wx1 * wy1 * wz1;
    }
    float wsum = pw[0] + pw[1] + pw[2] + pw[3] + pw[4] + pw[5] + pw[6] + pw[7];
    float wscale = __fdividef(1.0f, fmaxf(wsum, 1e-8f));

    float wty0 = 1.0f - ty, wty1 = ty;
    const char* basec = (const char*)base;

    float acc0 = 0.0f, acc1 = 0.0f, acc2 = 0.0f;

#pragma unroll
    for (int p = 0; p < 8; p++) {
        unsigned pb = pbyte[p];
        float wp = pw[p];
#pragma unroll
        for (int r = 0; r < 2; r++) {
            unsigned s = pb + (r ? rb1 : rb0);
            unsigned f = s & ~15u;
            float4 A = __ldg((const float4*)(basec + f));
            float4 B = __ldg((const float4*)(basec + f + 16));
            float E = 0.0f;
            if (k3) E = __ldg((const float*)(basec + f + 32));

            float c0 = k1 ? A.y : A.x;  c0 = k2 ? A.z : c0;  c0 = k3 ? A.w : c0;
            float c1 = k1 ? A.z : A.y;  c1 = k2 ? A.w : c1;  c1 = k3 ? B.x : c1;
            float c2 = k1 ? A.w : A.z;  c2 = k2 ? B.x : c2;  c2 = k3 ? B.y : c2;
            float c3 = k1 ? B.x : A.w;  c3 = k2 ? B.y : c3;  c3 = k3 ? B.z : c3;
            float c4 = k1 ? B.y : B.x;  c4 = k2 ? B.z : c4;  c4 = k3 ? B.w : c4;
            float c5 = k1 ? B.z : B.y;  c5 = k2 ? B.w : c5;  c5 = k3 ? E   : c5;

            float w = wp * (r ? wty1 : wty0);
            acc0 = fmaf(w, fmaf(gx0, c0, gx1 * c3), acc0);
            acc1 = fmaf(w, fmaf(gx0, c1, gx1 * c4), acc1);
            acc2 = fmaf(w, fmaf(gx0, c2, gx1 * c5), acc2);
        }
    }
    acc0 *= wscale; acc1 *= wscale; acc2 *= wscale;

    out[3 * i + 0] = __fdividef(10.0f, 1.0f + __expf(-acc0));
    out[3 * i + 1] = __fdividef(10.0f, 1.0f + __expf(-acc1));
    out[3 * i + 2] = __fdividef(10.0f, 1.0f + __expf(-acc2));
}

extern "C" void kernel_launch(void* const* d_in, const int* in_sizes, int n_in,
                              void* d_out, int out_size) {
    const float* xyz  = (const float*)d_in[0];
    const float* l    = (const float*)d_in[1];
    const float* base = (const float*)d_in[2];
    float* out = (float*)d_out;
    int n = in_sizes[0] / 3;
    int threads = 256;
    int blocks = (n + threads - 1) / threads;

    if (n <= NQ_CAP) {
        zero_counts_kernel<<<(NBUCKETS * PAD + 1023) / 1024, 1024>>>();
        hist_kernel<<<blocks, threads>>>(xyz, l, n);
        scan_kernel<<<1, 1024>>>();
        scatter_kernel<<<blocks, threads>>>(xyz, l, n);
        multienv_kernel<<<blocks, threads>>>(xyz, l, base, out, n, 1);
    } else {
        multienv_kernel<<<blocks, threads>>>(xyz, l, base, out, n, 0);
    }
}

// round 9
// speedup vs baseline: 1.2133x; 1.1813x over previous
#include <cuda_runtime.h>

#define R 128
#define PROBE_BYTES (6 * R * R * 3 * 4)   // 1179648
#define FACE_BYTES  (R * R * 3 * 4)       // 196608
#define NQ_CAP 524288

#define NB    3072                 // 6 faces * 128 rows * 4 sub-buckets
#define CAP   320                  // slots per bucket (avg fill ~171)
#define NSLOT (NB * CAP)           // 983040
#define OVERCAP NQ_CAP             // bulletproof overflow
#define PADC  32                   // counter pad: 128B stride

struct Rec { float x, y, z, lx, ly, lz; unsigned idx, pad; };

__device__ Rec      d_rec[NSLOT];
__device__ Rec      d_orec[OVERCAP];
__device__ unsigned d_cursor[NB * PADC];
__device__ unsigned d_overcount;

__global__ void zero_counts_kernel() {
    int t = blockIdx.x * blockDim.x + threadIdx.x;
    if (t < NB * PADC) d_cursor[t] = 0;
    if (t == 0) d_overcount = 0;
}

// key from raw l (face + row are scale-invariant); main kernel recomputes exactly.
__global__ __launch_bounds__(256) void scatter_kernel(
    const float* __restrict__ xyz, const float* __restrict__ l, int n)
{
    int i = blockIdx.x * blockDim.x + threadIdx.x;
    if (i >= n) return;
    float lx = l[3 * i + 0], ly = l[3 * i + 1], lz = l[3 * i + 2];
    float ax = fabsf(lx), ay = fabsf(ly), az = fabsf(lz);
    bool is_x = (ax >= ay) && (ax >= az);
    bool is_y = (!is_x) && (ay >= az);
    int face; float ma, tc;
    if (is_x)      { face = (lx >= 0.0f) ? 0 : 1; ma = ax; tc = -ly; }
    else if (is_y) { face = (ly >= 0.0f) ? 2 : 3; ma = ay; tc = (ly >= 0.0f) ? lz : -lz; }
    else           { face = (lz >= 0.0f) ? 4 : 5; ma = az; tc = -ly; }
    ma = fmaxf(ma, 1e-30f);
    float v = 0.5f * (tc / ma + 1.0f);
    int y0 = min(max((int)floorf(v * (float)R - 0.5f), 0), R - 1);
    int key = ((face * R + y0) << 2) | (i & 3);

    Rec r;
    r.x = xyz[3 * i + 0]; r.y = xyz[3 * i + 1]; r.z = xyz[3 * i + 2];
    r.lx = lx; r.ly = ly; r.lz = lz;
    r.idx = (unsigned)i; r.pad = 0u;

    unsigned rank = atomicAdd(&d_cursor[key * PADC], 1u);
    if (rank < CAP) {
        Rec* dst = &d_rec[key * CAP + rank];
        *(float4*)dst = *(float4*)&r;
        *((float4*)dst + 1) = *((float4*)&r + 1);
    } else {
        unsigned opos = atomicAdd(&d_overcount, 1u);
        Rec* dst = &d_orec[opos];
        *(float4*)dst = *(float4*)&r;
        *((float4*)dst + 1) = *((float4*)&r + 1);
    }
}

#define GRID 512

__device__ __forceinline__ void process_query(
    const Rec& q, const char* __restrict__ basec, float* __restrict__ out)
{
    float lx = q.lx, ly = q.ly, lz = q.lz;
    float dot = lx * lx + ly * ly + lz * lz;
    float inv = rsqrtf(fmaxf(dot, 1e-18f));
    float dx = lx * inv, dy = ly * inv, dz = lz * inv;

    float ax = fabsf(dx), ay = fabsf(dy), az = fabsf(dz);
    bool is_x = (ax >= ay) && (ax >= az);
    bool is_y = (!is_x) && (ay >= az);
    int face; float ma, sc, tc;
    if (is_x) {
        face = (dx >= 0.0f) ? 0 : 1; ma = ax;
        sc = (dx >= 0.0f) ? -dz : dz; tc = -dy;
    } else if (is_y) {
        face = (dy >= 0.0f) ? 2 : 3; ma = ay;
        sc = dx; tc = (dy >= 0.0f) ? dz : -dz;
    } else {
        face = (dz >= 0.0f) ? 4 : 5; ma = az;
        sc = (dz >= 0.0f) ? dx : -dx; tc = -dy;
    }
    ma = fmaxf(ma, 1e-9f);
    float rma = __fdividef(1.0f, ma);
    float u = 0.5f * (sc * rma + 1.0f);
    float v = 0.5f * (tc * rma + 1.0f);

    float fx = u * (float)R - 0.5f;
    float fy = v * (float)R - 0.5f;
    float x0f = floorf(fx), y0f = floorf(fy);
    float tx = fx - x0f, ty = fy - y0f;
    int x0 = min(max((int)x0f, 0), R - 1);
    int x1 = min(max((int)x0f + 1, 0), R - 1);
    int y0 = min(max((int)y0f, 0), R - 1);
    int y1 = min(max((int)y0f + 1, 0), R - 1);

    int cs   = min(x0, R - 2);
    int off0 = x0 - cs;
    int off1 = x1 - cs;
    float gx0 = (off0 ? 0.0f : (1.0f - tx)) + (off1 ? 0.0f : tx);
    float gx1 = 1.0f - gx0;

    unsigned rb0 = (unsigned)face * FACE_BYTES + (unsigned)(y0 * R + cs) * 12u;
    unsigned rb1 = (unsigned)face * FACE_BYTES + (unsigned)(y1 * R + cs) * 12u;

    int k = (int)((rb0 & 15u) >> 2);
    bool k1 = (k == 1), k2 = (k == 2), k3 = (k == 3);

    float px = q.x, py = q.y, pz = q.z;
    float cx = fminf(fmaxf(px * 7.0f, 0.0f), 7.0f);
    float cy = fminf(fmaxf(py * 7.0f, 0.0f), 7.0f);
    float cz = fminf(fmaxf(pz * 3.0f, 0.0f), 3.0f);
    int ix0 = (int)floorf(cx);
    int iy0 = (int)floorf(cy);
    int iz0 = (int)floorf(cz);
    int ix1 = min(ix0 + 1, 7);
    int iy1 = min(iy0 + 1, 7);
    int iz1 = min(iz0 + 1, 3);
    float gx = cx - (float)ix0;
    float gy = cy - (float)iy0;
    float gz = cz - (float)iz0;

    unsigned pbyte[8];
    float pw[8];
    {
        float wx0 = 1.0f - gx, wx1 = gx;
        float wy0 = 1.0f - gy, wy1 = gy;
        float wz0 = 1.0f - gz, wz1 = gz;
        unsigned bx0 = (unsigned)ix0 * 32u, bx1 = (unsigned)ix1 * 32u;
        unsigned by0 = (unsigned)iy0 * 4u,  by1 = (unsigned)iy1 * 4u;
        pbyte[0] = (bx0 + by0 + iz0) * (unsigned)PROBE_BYTES;  pw[0] = wx0 * wy0 * wz0;
        pbyte[1] = (bx0 + by0 + iz1) * (unsigned)PROBE_BYTES;  pw[1] = wx0 * wy0 * wz1;
        pbyte[2] = (bx0 + by1 + iz0) * (unsigned)PROBE_BYTES;  pw[2] = wx0 * wy1 * wz0;
        pbyte[3] = (bx0 + by1 + iz1) * (unsigned)PROBE_BYTES;  pw[3] = wx0 * wy1 * wz1;
        pbyte[4] = (bx1 + by0 + iz0) * (unsigned)PROBE_BYTES;  pw[4] = wx1 * wy0 * wz0;
        pbyte[5] = (bx1 + by0 + iz1) * (unsigned)PROBE_BYTES;  pw[5] = wx1 * wy0 * wz1;
        pbyte[6] = (bx1 + by1 + iz0) * (unsigned)PROBE_BYTES;  pw[6] = wx1 * wy1 * wz0;
        pbyte[7] = (bx1 + by1 + iz1) * (unsigned)PROBE_BYTES;  pw[7] = wx1 * wy1 * wz1;
    }
    float wsum = pw[0] + pw[1] + pw[2] + pw[3] + pw[4] + pw[5] + pw[6] + pw[7];
    float wscale = __fdividef(1.0f, fmaxf(wsum, 1e-8f));

    float wty0 = 1.0f - ty, wty1 = ty;

    float acc0 = 0.0f, acc1 = 0.0f, acc2 = 0.0f;
#pragma unroll
    for (int p = 0; p < 8; p++) {
        unsigned pb = pbyte[p];
        float wp = pw[p];
#pragma unroll
        for (int r = 0; r < 2; r++) {
            unsigned s = pb + (r ? rb1 : rb0);
            unsigned f = s & ~15u;
            float4 A = __ldg((const float4*)(basec + f));
            float4 B = __ldg((const float4*)(basec + f + 16));
            float E = 0.0f;
            if (k3) E = __ldg((const float*)(basec + f + 32));

            float c0 = k1 ? A.y : A.x;  c0 = k2 ? A.z : c0;  c0 = k3 ? A.w : c0;
            float c1 = k1 ? A.z : A.y;  c1 = k2 ? A.w : c1;  c1 = k3 ? B.x : c1;
            float c2 = k1 ? A.w : A.z;  c2 = k2 ? B.x : c2;  c2 = k3 ? B.y : c2;
            float c3 = k1 ? B.x : A.w;  c3 = k2 ? B.y : c3;  c3 = k3 ? B.z : c3;
            float c4 = k1 ? B.y : B.x;  c4 = k2 ? B.z : c4;  c4 = k3 ? B.w : c4;
            float c5 = k1 ? B.z : B.y;  c5 = k2 ? B.w : c5;  c5 = k3 ? E   : c5;

            float w = wp * (r ? wty1 : wty0);
            acc0 = fmaf(w, fmaf(gx0, c0, gx1 * c3), acc0);
            acc1 = fmaf(w, fmaf(gx0, c1, gx1 * c4), acc1);
            acc2 = fmaf(w, fmaf(gx0, c2, gx1 * c5), acc2);
        }
    }
    acc0 *= wscale; acc1 *= wscale; acc2 *= wscale;

    unsigned o = q.idx * 3u;
    out[o + 0] = __fdividef(10.0f, 1.0f + __expf(-acc0));
    out[o + 1] = __fdividef(10.0f, 1.0f + __expf(-acc1));
    out[o + 2] = __fdividef(10.0f, 1.0f + __expf(-acc2));
}

// Persistent: 512 CTAs walk slots in sorted order; concurrent window ~80MB < L2.
__global__ __launch_bounds__(256) void multienv_sorted_kernel(
    const float* __restrict__ base, float* __restrict__ out)
{
    const char* basec = (const char*)base;
    unsigned stride = GRID * 256;
    unsigned over = d_overcount;
    for (unsigned slot = blockIdx.x * 256 + threadIdx.x;
         slot < NSLOT + OVERCAP; slot += stride) {
        Rec q;
        if (slot < NSLOT) {
            unsigned b = slot / CAP;
            unsigned s = slot - b * CAP;
            unsigned cnt = d_cursor[b * PADC];
            if (s >= min(cnt, (unsigned)CAP)) continue;
            const Rec* src = &d_rec[slot];
            *(float4*)&q = __ldg((const float4*)src);
            *((float4*)&q + 1) = __ldg((const float4*)src + 1);
        } else {
            unsigned s = slot - NSLOT;
            if (s >= over) continue;
            const Rec* src = &d_orec[s];
            *(float4*)&q = __ldg((const float4*)src);
            *((float4*)&q + 1) = __ldg((const float4*)src + 1);
        }
        process_query(q, basec, out);
    }
}

// fallback: direct (unsorted) version
__global__ __launch_bounds__(256) void multienv_direct_kernel(
    const float* __restrict__ xyz, const float* __restrict__ l,
    const float* __restrict__ base, float* __restrict__ out, int n)
{
    int i = blockIdx.x * blockDim.x + threadIdx.x;
    if (i >= n) return;
    Rec q;
    q.x = xyz[3 * i + 0]; q.y = xyz[3 * i + 1]; q.z = xyz[3 * i + 2];
    q.lx = l[3 * i + 0];  q.ly = l[3 * i + 1];  q.lz = l[3 * i + 2];
    q.idx = (unsigned)i;
    process_query(q, (const char*)base, out);
}

extern "C" void kernel_launch(void* const* d_in, const int* in_sizes, int n_in,
                              void* d_out, int out_size) {
    const float* xyz  = (const float*)d_in[0];
    const float* l    = (const float*)d_in[1];
    const float* base = (const float*)d_in[2];
    float* out = (float*)d_out;
    int n = in_sizes[0] / 3;
    int threads = 256;
    int blocks = (n + threads - 1) / threads;

    if (n <= NQ_CAP) {
        zero_counts_kernel<<<(NB * PADC + 1023) / 1024, 1024>>>();
        scatter_kernel<<<blocks, threads>>>(xyz, l, n);
        multienv_sorted_kernel<<<GRID, threads>>>(base, out);
    } else {
        multienv_direct_kernel<<<blocks, threads>>>(xyz, l, base, out, n);
    }
}